// round 1
// baseline (speedup 1.0000x reference)
#include <cuda_runtime.h>
#include <cuda_bf16.h>

#define BB 64
#define LL 4096
#define DD 256
#define VV 33

// Fully fused: per-batch histogram over valid prefix -> pooled = hist @ emb
// -> h = relu(pooled@W1+b1) -> out = relu(h@W2+b2).
// One CTA per batch row, 256 threads (one per feature dim).
__global__ __launch_bounds__(256, 4) void palace_prot_net_fused(
    const void* __restrict__ Xraw,       // [B, L] int32 or int64 (runtime detect)
    const void* __restrict__ VLraw,      // [B]    int32 or int64
    const float* __restrict__ emb,       // [33, 256]
    const float* __restrict__ W1,        // [256, 256]
    const float* __restrict__ b1,        // [256]
    const float* __restrict__ W2,        // [256, 256]
    const float* __restrict__ b2,        // [256]
    float* __restrict__ out)             // [B, 256]
{
    const int b   = blockIdx.x;
    const int tid = threadIdx.x;

    __shared__ int   counts[VV];
    __shared__ float cntf[VV];
    __shared__ float pbuf[DD];
    __shared__ float hbuf[DD];

    // ---- dtype detection (int64 vs int32 token buffer) ----
    // Probe odd 32-bit words among the first 2048 words (always in-bounds for
    // either dtype). int64 tokens (values < 33) have zero high words; int32
    // tokens at odd indices are random in [0,33).
    const int* xi = (const int*)Xraw;
    int nz = 0;
    #pragma unroll
    for (int i = tid; i < 1024; i += 256) nz |= xi[2 * i + 1];
    const int is64 = (__syncthreads_or(nz) == 0);

    // ---- valid length for this row ----
    long long vl;
    if (is64) vl = ((const long long*)VLraw)[b];
    else      vl = (long long)((const int*)VLraw)[b];

    // ---- histogram of tokens in valid prefix ----
    if (tid < VV) counts[tid] = 0;
    __syncthreads();

    const size_t base = (size_t)b * LL;
    if (is64) {
        // little-endian: low word of each int64 holds the token (0..32)
        for (int l = tid; l < LL; l += 256) {
            if (l < vl) atomicAdd(&counts[xi[2 * (base + l)]], 1);
        }
    } else {
        for (int l = tid; l < LL; l += 256) {
            if (l < vl) atomicAdd(&counts[xi[base + l]], 1);
        }
    }
    __syncthreads();
    if (tid < VV) cntf[tid] = (float)counts[tid];
    __syncthreads();

    // ---- pooled[b][tid] = sum_v cnt[v] * emb[v][tid] ----
    {
        float acc = 0.f;
        #pragma unroll
        for (int v = 0; v < VV; v++)
            acc = fmaf(cntf[v], emb[v * DD + tid], acc);
        pbuf[tid] = acc;
    }
    __syncthreads();

    // ---- layer 1: h = relu(pooled @ W1 + b1) ----
    {
        float a0 = 0.f, a1 = 0.f, a2 = 0.f, a3 = 0.f;
        #pragma unroll 8
        for (int d = 0; d < DD; d += 4) {
            a0 = fmaf(pbuf[d + 0], W1[(d + 0) * DD + tid], a0);
            a1 = fmaf(pbuf[d + 1], W1[(d + 1) * DD + tid], a1);
            a2 = fmaf(pbuf[d + 2], W1[(d + 2) * DD + tid], a2);
            a3 = fmaf(pbuf[d + 3], W1[(d + 3) * DD + tid], a3);
        }
        hbuf[tid] = fmaxf((a0 + a1) + (a2 + a3) + b1[tid], 0.f);
    }
    __syncthreads();

    // ---- layer 2: out = relu(h @ W2 + b2) ----
    {
        float a0 = 0.f, a1 = 0.f, a2 = 0.f, a3 = 0.f;
        #pragma unroll 8
        for (int d = 0; d < DD; d += 4) {
            a0 = fmaf(hbuf[d + 0], W2[(d + 0) * DD + tid], a0);
            a1 = fmaf(hbuf[d + 1], W2[(d + 1) * DD + tid], a1);
            a2 = fmaf(hbuf[d + 2], W2[(d + 2) * DD + tid], a2);
            a3 = fmaf(hbuf[d + 3], W2[(d + 3) * DD + tid], a3);
        }
        out[b * DD + tid] = fmaxf((a0 + a1) + (a2 + a3) + b2[tid], 0.f);
    }
}

extern "C" void kernel_launch(void* const* d_in, const int* in_sizes, int n_in,
                              void* d_out, int out_size) {
    // metadata order: X, valid_lens, emb, W1, b1, W2, b2
    const void*  X   = d_in[0];
    const void*  VL  = d_in[1];
    const float* emb = (const float*)d_in[2];
    const float* W1  = (const float*)d_in[3];
    const float* b1  = (const float*)d_in[4];
    const float* W2  = (const float*)d_in[5];
    const float* b2  = (const float*)d_in[6];
    float* out = (float*)d_out;

    palace_prot_net_fused<<<BB, 256>>>(X, VL, emb, W1, b1, W2, b2, out);
}

// round 2
// speedup vs baseline: 1.1974x; 1.1974x over previous
#include <cuda_runtime.h>
#include <cuda_bf16.h>

#define BB 64
#define LL 4096
#define DD 256
#define VV 33
#define NT 1024
#define NW 32   // warps per CTA

// Fully fused, one CTA per batch row, 1024 threads.
// Phase 1: per-warp privatized histogram over valid prefix -> counts
// Phase 2: pooled = counts @ emb   (33 FMA per feature)
// Phase 3: layer1 with K split 4 ways across thread groups + smem reduce
// Phase 4: layer2 same
__global__ __launch_bounds__(NT, 1) void palace_prot_net_fused(
    const void* __restrict__ Xraw,       // [B, L] int32 or int64 (runtime detect)
    const void* __restrict__ VLraw,      // [B]    int32 or int64
    const float* __restrict__ emb,       // [33, 256]
    const float* __restrict__ W1,        // [256, 256]
    const float* __restrict__ b1,        // [256]
    const float* __restrict__ W2,        // [256, 256]
    const float* __restrict__ b2,        // [256]
    float* __restrict__ out)             // [B, 256]
{
    const int b    = blockIdx.x;
    const int tid  = threadIdx.x;
    const int wid  = tid >> 5;

    __shared__ int   whist[NW * VV];   // per-warp private histograms
    __shared__ float cntf[VV];
    __shared__ float pbuf[DD];
    __shared__ float hbuf[DD];
    __shared__ float part[3 * DD];     // k-partition partials (kp 1..3)

    // ---- dtype detection (int64 vs int32 token buffer) ----
    // Probe odd 32-bit words of the first 1024 tokens of row 0 (in-bounds for
    // either dtype). int64 tokens (< 33) have zero high words; int32 tokens at
    // odd word indices are random in [0,33) -> some word is nonzero w.h.p.
    const int* xi = (const int*)Xraw;
    int nz = xi[2 * tid + 1];
    const int is64 = (__syncthreads_or(nz) == 0);

    // ---- valid length ----
    long long vl;
    if (is64) vl = ((const long long*)VLraw)[b];
    else      vl = (long long)((const int*)VLraw)[b];

    // ---- histogram: per-warp private bins, vectorized token loads ----
    for (int i = tid; i < NW * VV; i += NT) whist[i] = 0;
    __syncthreads();

    const size_t base = (size_t)b * LL;
    {
        int* myh = &whist[wid * VV];
        const int l0 = tid * 4;                 // 4 contiguous tokens per thread
        if (is64) {
            // low words of int64 tokens; two int4 loads cover 4 tokens
            const int4* p = (const int4*)(xi + 2 * (base + l0));
            int4 v0 = p[0], v1 = p[1];
            if (l0 + 0 < vl) atomicAdd(&myh[v0.x], 1);
            if (l0 + 1 < vl) atomicAdd(&myh[v0.z], 1);
            if (l0 + 2 < vl) atomicAdd(&myh[v1.x], 1);
            if (l0 + 3 < vl) atomicAdd(&myh[v1.z], 1);
        } else {
            int4 v = *(const int4*)(xi + base + l0);
            if (l0 + 0 < vl) atomicAdd(&myh[v.x], 1);
            if (l0 + 1 < vl) atomicAdd(&myh[v.y], 1);
            if (l0 + 2 < vl) atomicAdd(&myh[v.z], 1);
            if (l0 + 3 < vl) atomicAdd(&myh[v.w], 1);
        }
    }
    __syncthreads();

    // ---- reduce private histograms ----
    if (tid < VV) {
        int s = 0;
        #pragma unroll
        for (int w = 0; w < NW; w++) s += whist[w * VV + tid];
        cntf[tid] = (float)s;
    }
    __syncthreads();

    // ---- pooled[tid] = sum_v cnt[v] * emb[v][tid] ----
    if (tid < DD) {
        float acc = 0.f;
        #pragma unroll
        for (int v = 0; v < VV; v++)
            acc = fmaf(cntf[v], emb[v * DD + tid], acc);
        pbuf[tid] = acc;
    }
    __syncthreads();

    const int j  = tid & (DD - 1);   // output column
    const int kp = tid >> 8;         // k-partition 0..3 (64 k's each)
    const int k0 = kp << 6;

    // ---- layer 1: h = relu(pooled @ W1 + b1), K split 4 ways ----
    {
        float acc = 0.f;
        const float* wcol = W1 + (size_t)k0 * DD + j;
        #pragma unroll 16
        for (int i = 0; i < 64; i++)
            acc = fmaf(pbuf[k0 + i], wcol[i * DD], acc);
        if (kp) part[(kp - 1) * DD + j] = acc;
        __syncthreads();
        if (kp == 0) {
            acc += part[j] + part[DD + j] + part[2 * DD + j];
            hbuf[j] = fmaxf(acc + b1[j], 0.f);
        }
        __syncthreads();
    }

    // ---- layer 2: out = relu(h @ W2 + b2), K split 4 ways ----
    {
        float acc = 0.f;
        const float* wcol = W2 + (size_t)k0 * DD + j;
        #pragma unroll 16
        for (int i = 0; i < 64; i++)
            acc = fmaf(hbuf[k0 + i], wcol[i * DD], acc);
        if (kp) part[(kp - 1) * DD + j] = acc;
        __syncthreads();
        if (kp == 0) {
            acc += part[j] + part[DD + j] + part[2 * DD + j];
            out[b * DD + j] = fmaxf(acc + b2[j], 0.f);
        }
    }
}

extern "C" void kernel_launch(void* const* d_in, const int* in_sizes, int n_in,
                              void* d_out, int out_size) {
    // metadata order: X, valid_lens, emb, W1, b1, W2, b2
    const void*  X   = d_in[0];
    const void*  VL  = d_in[1];
    const float* emb = (const float*)d_in[2];
    const float* W1  = (const float*)d_in[3];
    const float* b1  = (const float*)d_in[4];
    const float* W2  = (const float*)d_in[5];
    const float* b2  = (const float*)d_in[6];
    float* out = (float*)d_out;

    palace_prot_net_fused<<<BB, NT>>>(X, VL, emb, W1, b1, W2, b2, out);
}